// round 6
// baseline (speedup 1.0000x reference)
#include <cuda_runtime.h>
#include <cstdint>

#define N_ROWS   10000
#define NPAD     10112          // padded for HnT tiles (10112 = 79*128)
#define D_IN     128
#define HID      32
#define EMB      16
#define STRIPS   4
#define NJT      79             // ceil(10000/128) column tiles
#define BM       80             // rows per CTA tile (125 * 80 = 10000 exactly)
#define BN       128            // cols per CTA tile

// ---------------- static device scratch (no allocations allowed) ----------------
__device__ __align__(16) float g_Hn [NPAD * EMB];      // normalized embeddings, row-major
__device__ __align__(16) float g_HnT[EMB * NPAD];      // transposed (k-major)
__device__ __align__(16) float g_Zpart[STRIPS * N_ROWS];
__device__ __align__(16) float g_invZ[N_ROWS];

// ======================================================================
// Kernel 1: encoder.  H = relu(X@W1 + b1)@W2 + b2 ; Hn = H / max(||H||,1e-12)
// One warp per row; 8 warps / block. Also zeroes the pad rows of Hn/HnT.
// ======================================================================
__global__ void __launch_bounds__(256) encoder_kernel(
    const float* __restrict__ X, const float* __restrict__ W1,
    const float* __restrict__ b1, const float* __restrict__ W2,
    const float* __restrict__ b2, float* __restrict__ Hout)
{
    __shared__ float sW1[D_IN * HID];   // [k][u]
    __shared__ float sW2[HID * EMB];    // [u][e]
    __shared__ float sb1[HID];
    __shared__ float sb2[EMB];
    __shared__ float sX[8][D_IN];
    __shared__ float sH1[8][HID];

    const int tid = threadIdx.x;
    for (int i = tid; i < D_IN * HID; i += 256) sW1[i] = W1[i];
    for (int i = tid; i < HID * EMB;  i += 256) sW2[i] = W2[i];   // 512 elems, 256 threads
    if (tid < HID)       sb1[tid] = b1[tid];
    if (tid < EMB)       sb2[tid] = b2[tid];
    __syncthreads();

    const int w    = tid >> 5;
    const int lane = tid & 31;
    const int row  = blockIdx.x * 8 + w;
    if (row >= NPAD) return;

    if (row >= N_ROWS) {                 // zero pad rows (so padded logits are 0)
        if (lane < EMB) {
            g_Hn[row * EMB + lane]   = 0.f;
            g_HnT[lane * NPAD + row] = 0.f;
        }
        return;
    }

    // stage X row (coalesced)
    #pragma unroll
    for (int q = 0; q < 4; ++q) sX[w][lane + 32 * q] = X[(size_t)row * D_IN + lane + 32 * q];
    __syncwarp();

    // hidden layer: lane u computes h1[u]
    float h1 = sb1[lane];
    #pragma unroll
    for (int k = 0; k < D_IN; ++k) h1 = fmaf(sX[w][k], sW1[k * HID + lane], h1);
    h1 = fmaxf(h1, 0.f);
    sH1[w][lane] = h1;
    __syncwarp();

    // output layer: lane e (duplicated in both half-warps) computes h[e]
    const int e = lane & 15;
    float h = sb2[e];
    #pragma unroll
    for (int u = 0; u < HID; ++u) h = fmaf(sH1[w][u], sW2[u * EMB + e], h);

    // L2 norm across the 16 lanes of each half-warp
    float ss = h * h;
    ss += __shfl_xor_sync(0xffffffffu, ss, 1);
    ss += __shfl_xor_sync(0xffffffffu, ss, 2);
    ss += __shfl_xor_sync(0xffffffffu, ss, 4);
    ss += __shfl_xor_sync(0xffffffffu, ss, 8);
    const float inv = 1.f / fmaxf(sqrtf(ss), 1e-12f);

    if (lane < EMB) {
        Hout[(size_t)row * EMB + e]   = h;
        g_Hn[row * EMB + e]           = h * inv;
        g_HnT[e * NPAD + row]         = h * inv;
    }
}

// ======================================================================
// Main passes.  Tile: BM=80 rows x BN=128 cols, CTA 256 threads.
// Thread (tx,ty): rows i0 + ty + 16r (r<5), cols j0 + tx + 16c (c<CMAX).
//   -> smem reads conflict-free, global A reads 64B-contiguous per half-warp.
// lc (log2 domain) = kA * lg2(A+1e-12) + kB * dot16(Hn_i, Hn_j)
//   kA = alpha,  kB = (1-alpha)/(tau*ln2);  u = ex2(lc).  No max needed
//   (lc bounded in ~[-10.5,-1.9], fp32-safe).
// ======================================================================
__device__ __forceinline__ void prefetch_tile(float* dst, int j0)
{
    const int tid = threadIdx.x;
    #pragma unroll
    for (int q = 0; q < 2; ++q) {
        const int s  = tid + q * 256;        // 512 float4 slots: 16 k-rows x 32
        const int k  = s >> 5;
        const int cw = s & 31;
        const float* src = g_HnT + k * NPAD + j0 + 4 * cw;
        unsigned dsts = (unsigned)__cvta_generic_to_shared(dst + k * BN + 4 * cw);
        asm volatile("cp.async.ca.shared.global [%0], [%1], 16;" :: "r"(dsts), "l"(src) : "memory");
    }
    asm volatile("cp.async.commit_group;" ::: "memory");
}

template<int CMAX, bool WRITE>
__device__ __forceinline__ void tile_compute(
    const float* __restrict__ A, float* __restrict__ Wout,
    const float* sHnI, const float* sHnT,
    int i0, int j0, int ty, int tx,
    float kA, float kB, float zacc[5], const float* invz)
{
    // stream A tile into registers early (hide DRAM latency under the dot)
    float a[5][CMAX];
    #pragma unroll
    for (int r = 0; r < 5; ++r) {
        const float* ap = A + (size_t)(i0 + ty + 16 * r) * N_ROWS + (j0 + tx);
        #pragma unroll
        for (int c = 0; c < CMAX; ++c) a[r][c] = __ldg(ap + 16 * c);
    }

    float acc[5][CMAX] = {};
    #pragma unroll
    for (int k = 0; k < EMB; ++k) {
        float av[5], bv[CMAX];
        #pragma unroll
        for (int r = 0; r < 5; ++r)    av[r] = sHnI[(ty + 16 * r) * EMB + k];
        #pragma unroll
        for (int c = 0; c < CMAX; ++c) bv[c] = sHnT[k * BN + tx + 16 * c];
        #pragma unroll
        for (int r = 0; r < 5; ++r)
            #pragma unroll
            for (int c = 0; c < CMAX; ++c)
                acc[r][c] = fmaf(av[r], bv[c], acc[r][c]);
    }

    #pragma unroll
    for (int r = 0; r < 5; ++r) {
        float zr = 0.f;
        float* wp = Wout + (size_t)(i0 + ty + 16 * r) * N_ROWS + (j0 + tx);
        #pragma unroll
        for (int c = 0; c < CMAX; ++c) {
            float lg;
            asm("lg2.approx.f32 %0, %1;" : "=f"(lg) : "f"(a[r][c] + 1e-12f));
            const float t = fmaf(kA, lg, kB * acc[r][c]);
            float u;
            asm("ex2.approx.f32 %0, %1;" : "=f"(u) : "f"(t));
            if (WRITE) wp[16 * c] = u * invz[r];
            else       zr += u;
        }
        if (!WRITE) zacc[r] += zr;
    }
}

template<bool WRITE>
__global__ void __launch_bounds__(256, 2) pass_kernel(
    const float* __restrict__ A, float* __restrict__ Wout,
    const float* __restrict__ p_log_tau, const float* __restrict__ p_raw_alpha)
{
    __shared__ __align__(16) float sHnI[BM * EMB];
    __shared__ __align__(16) float sHnT[2][EMB * BN];

    const int tid   = threadIdx.x;
    const int tx    = tid & 15;
    const int ty    = tid >> 4;
    const int strip = blockIdx.x;
    const int i0    = blockIdx.y * BM;

    const float alpha = 1.f / (1.f + __expf(-p_raw_alpha[0]));
    const float tau   = fminf(fmaxf(__expf(p_log_tau[0]), 0.1f), 10.f);
    const float kA    = alpha;
    const float kB    = (1.f - alpha) / (tau * 0.6931471805599453f);

    // load this CTA's 80 Hn rows (visible after first __syncthreads)
    for (int t = tid; t < BM * EMB / 4; t += 256)
        *(float4*)(sHnI + 4 * t) = *(const float4*)(g_Hn + i0 * EMB + 4 * t);

    float invz[5];
    if (WRITE) {
        #pragma unroll
        for (int r = 0; r < 5; ++r) invz[r] = g_invZ[i0 + ty + 16 * r];
    }
    float zacc[5] = {0.f, 0.f, 0.f, 0.f, 0.f};

    prefetch_tile(&sHnT[0][0], strip * BN);
    int buf = 0;
    for (int jt = strip; jt < NJT; jt += STRIPS) {
        const int nxt = jt + STRIPS;
        if (nxt < NJT) {
            prefetch_tile(&sHnT[buf ^ 1][0], nxt * BN);
            asm volatile("cp.async.wait_group 1;" ::: "memory");
        } else {
            asm volatile("cp.async.wait_group 0;" ::: "memory");
        }
        __syncthreads();
        if (jt == NJT - 1)      // last tile has exactly 16 cols -> CMAX=1, no predicates
            tile_compute<1, WRITE>(A, Wout, sHnI, &sHnT[buf][0], i0, jt * BN, ty, tx, kA, kB, zacc, invz);
        else
            tile_compute<8, WRITE>(A, Wout, sHnI, &sHnT[buf][0], i0, jt * BN, ty, tx, kA, kB, zacc, invz);
        __syncthreads();
        buf ^= 1;
    }

    if (!WRITE) {
        #pragma unroll
        for (int r = 0; r < 5; ++r) {
            float z = zacc[r];
            z += __shfl_xor_sync(0xffffffffu, z, 1);
            z += __shfl_xor_sync(0xffffffffu, z, 2);
            z += __shfl_xor_sync(0xffffffffu, z, 4);
            z += __shfl_xor_sync(0xffffffffu, z, 8);
            if (tx == 0) g_Zpart[strip * N_ROWS + i0 + ty + 16 * r] = z;
        }
    }
}

// ======================================================================
// Kernel 3: invZ[i] = 1 / sum_s Zpart[s][i]   (deterministic reduction)
// ======================================================================
__global__ void zreduce_kernel()
{
    const int i = blockIdx.x * 256 + threadIdx.x;
    if (i < N_ROWS) {
        float z = g_Zpart[i] + g_Zpart[N_ROWS + i]
                + g_Zpart[2 * N_ROWS + i] + g_Zpart[3 * N_ROWS + i];
        g_invZ[i] = 1.f / z;
    }
}

// ======================================================================
extern "C" void kernel_launch(void* const* d_in, const int* in_sizes, int n_in,
                              void* d_out, int out_size)
{
    (void)in_sizes; (void)n_in; (void)out_size;
    const float* X         = (const float*)d_in[0];
    const float* A         = (const float*)d_in[1];
    const float* W1        = (const float*)d_in[2];
    const float* b1        = (const float*)d_in[3];
    const float* W2        = (const float*)d_in[4];
    const float* b2        = (const float*)d_in[5];
    const float* log_tau   = (const float*)d_in[6];
    const float* raw_alpha = (const float*)d_in[7];

    float* out  = (float*)d_out;
    float* Wout = out;                                   // (N, N) first
    float* Hout = out + (size_t)N_ROWS * N_ROWS;         // (N, EMB) second

    encoder_kernel<<<NPAD / 8, 256>>>(X, W1, b1, W2, b2, Hout);
    pass_kernel<false><<<dim3(STRIPS, N_ROWS / BM), 256>>>(A, Wout, log_tau, raw_alpha);
    zreduce_kernel<<<(N_ROWS + 255) / 256, 256>>>();
    pass_kernel<true ><<<dim3(STRIPS, N_ROWS / BM), 256>>>(A, Wout, log_tau, raw_alpha);
}

// round 7
// speedup vs baseline: 1.0305x; 1.0305x over previous
#include <cuda_runtime.h>
#include <cstdint>

#define N_ROWS   10000
#define NPAD     10112          // padded for HnT tiles (10112 = 79*128)
#define D_IN     128
#define HID      32
#define EMB      16
#define STRIPS   3              // 3*125 = 375 CTAs <= 444 slots @ occ3 -> single wave
#define NJT      79             // ceil(10000/128) column tiles
#define BM       80             // rows per CTA tile (125 * 80 = 10000 exactly)
#define BN       128            // cols per CTA tile

typedef unsigned long long ull;

// ---------------- static device scratch (no allocations allowed) ----------------
__device__ __align__(16) float g_Hn  [NPAD * EMB];     // normalized embeddings, row-major
__device__ __align__(16) float g_HnTs[EMB * NPAD];     // transposed, PRE-SCALED by kB
__device__ __align__(16) float g_Zpart[STRIPS * N_ROWS];

// ---------------- f32x2 helpers (sm_103a packed fp32) ----------------
__device__ __forceinline__ ull f2pk(float lo, float hi) {
    ull r; asm("mov.b64 %0, {%1, %2};" : "=l"(r) : "f"(lo), "f"(hi)); return r;
}
__device__ __forceinline__ void f2up(ull v, float& lo, float& hi) {
    asm("mov.b64 {%0, %1}, %2;" : "=f"(lo), "=f"(hi) : "l"(v));
}
__device__ __forceinline__ ull ffma2(ull a, ull b, ull c) {
    ull d; asm("fma.rn.f32x2 %0, %1, %2, %3;" : "=l"(d) : "l"(a), "l"(b), "l"(c)); return d;
}
__device__ __forceinline__ ull fadd2(ull a, ull b) {
    ull d; asm("add.rn.f32x2 %0, %1, %2;" : "=l"(d) : "l"(a), "l"(b)); return d;
}

// ======================================================================
// Kernel 1: encoder.  H = relu(X@W1 + b1)@W2 + b2 ; Hn = H / max(||H||,1e-12)
// Writes g_Hn (unscaled) and g_HnTs (scaled by kB = (1-alpha)/(tau*ln2)).
// ======================================================================
__global__ void __launch_bounds__(256) encoder_kernel(
    const float* __restrict__ X, const float* __restrict__ W1,
    const float* __restrict__ b1, const float* __restrict__ W2,
    const float* __restrict__ b2, float* __restrict__ Hout,
    const float* __restrict__ p_log_tau, const float* __restrict__ p_raw_alpha)
{
    __shared__ float sW1[D_IN * HID];   // [k][u]
    __shared__ float sW2[HID * EMB];    // [u][e]
    __shared__ float sb1[HID];
    __shared__ float sb2[EMB];
    __shared__ float sX[8][D_IN];
    __shared__ float sH1[8][HID];

    const int tid = threadIdx.x;
    for (int i = tid; i < D_IN * HID; i += 256) sW1[i] = W1[i];
    for (int i = tid; i < HID * EMB;  i += 256) sW2[i] = W2[i];
    if (tid < HID) sb1[tid] = b1[tid];
    if (tid < EMB) sb2[tid] = b2[tid];
    __syncthreads();

    const int w    = tid >> 5;
    const int lane = tid & 31;
    const int row  = blockIdx.x * 8 + w;
    if (row >= NPAD) return;

    if (row >= N_ROWS) {                 // zero pad rows (so padded logits are 0)
        if (lane < EMB) {
            g_Hn [row * EMB + lane]  = 0.f;
            g_HnTs[lane * NPAD + row] = 0.f;
        }
        return;
    }

    // stage X row (coalesced)
    #pragma unroll
    for (int q = 0; q < 4; ++q) sX[w][lane + 32 * q] = X[(size_t)row * D_IN + lane + 32 * q];
    __syncwarp();

    // hidden layer: lane u computes h1[u]
    float h1 = sb1[lane];
    #pragma unroll
    for (int k = 0; k < D_IN; ++k) h1 = fmaf(sX[w][k], sW1[k * HID + lane], h1);
    h1 = fmaxf(h1, 0.f);
    sH1[w][lane] = h1;
    __syncwarp();

    // output layer: lane e (duplicated in both half-warps) computes h[e]
    const int e = lane & 15;
    float h = sb2[e];
    #pragma unroll
    for (int u = 0; u < HID; ++u) h = fmaf(sH1[w][u], sW2[u * EMB + e], h);

    // L2 norm across the 16 lanes of each half-warp
    float ss = h * h;
    ss += __shfl_xor_sync(0xffffffffu, ss, 1);
    ss += __shfl_xor_sync(0xffffffffu, ss, 2);
    ss += __shfl_xor_sync(0xffffffffu, ss, 4);
    ss += __shfl_xor_sync(0xffffffffu, ss, 8);
    const float inv = 1.f / fmaxf(sqrtf(ss), 1e-12f);

    if (lane < EMB) {
        const float alpha = 1.f / (1.f + __expf(-p_raw_alpha[0]));
        const float tau   = fminf(fmaxf(__expf(p_log_tau[0]), 0.1f), 10.f);
        const float kB    = (1.f - alpha) / (tau * 0.6931471805599453f);
        Hout[(size_t)row * EMB + e] = h;
        g_Hn [row * EMB + e]        = h * inv;
        g_HnTs[e * NPAD + row]      = h * inv * kB;
    }
}

// ======================================================================
// Main passes.  Tile: BM=80 rows x BN=128 cols, CTA 256 threads, occ 3.
// Thread (tx,ty): rows i0+ty+16r (r<5); col PAIRS j0 + 2tx + 32c.
// All A/W accesses are 64-bit; dot runs on fma.rn.f32x2 (FFMA2).
// lc (log2 domain) = kA*lg2(A+1e-12) + dot16(Hn_i, kB*Hn_j); u = ex2(lc).
// No row-max needed: lc bounded in ~[-10.5, 0.9], fp32-safe.
// ======================================================================
__device__ __forceinline__ void prefetch_tile(float* dst, int j0)
{
    const int tid = threadIdx.x;
    #pragma unroll
    for (int q = 0; q < 2; ++q) {
        const int s  = tid + q * 256;        // 512 float4 slots: 16 k-rows x 32
        const int k  = s >> 5;
        const int cw = s & 31;
        const float* src = g_HnTs + k * NPAD + j0 + 4 * cw;
        unsigned dsts = (unsigned)__cvta_generic_to_shared(dst + k * BN + 4 * cw);
        asm volatile("cp.async.ca.shared.global [%0], [%1], 16;" :: "r"(dsts), "l"(src) : "memory");
    }
    asm volatile("cp.async.commit_group;" ::: "memory");
}

template<int CP, bool WRITE>
__device__ __forceinline__ void tile_compute(
    const float* __restrict__ A, float* __restrict__ Wout,
    const ull* sHnI2, const float* sT,     // sT: smem tile base for this half
    int i0, int j0, int ty, int tx,
    float kA, ull eps2, float zacc[5], const float invz[5])
{
    // batch A pair-loads (LDG.64) up front: DRAM latency hidden under the dot
    ull a2[5][CP];
    #pragma unroll
    for (int r = 0; r < 5; ++r) {
        const ull* ap = (const ull*)(A + (size_t)(i0 + ty + 16 * r) * N_ROWS + j0 + 2 * tx);
        #pragma unroll
        for (int c = 0; c < CP; ++c) a2[r][c] = __ldg(ap + 16 * c);
    }

    ull acc[5][CP];
    #pragma unroll
    for (int r = 0; r < 5; ++r)
        #pragma unroll
        for (int c = 0; c < CP; ++c) acc[r][c] = 0ull;   // (0.f, 0.f)

    #pragma unroll
    for (int k = 0; k < EMB; ++k) {
        ull av[5], bv[CP];
        #pragma unroll
        for (int r = 0; r < 5; ++r)  av[r] = sHnI2[(ty + 16 * r) * EMB + k];
        #pragma unroll
        for (int c = 0; c < CP; ++c) bv[c] = *(const ull*)(sT + k * BN + 2 * tx + 32 * c);
        #pragma unroll
        for (int r = 0; r < 5; ++r)
            #pragma unroll
            for (int c = 0; c < CP; ++c)
                acc[r][c] = ffma2(av[r], bv[c], acc[r][c]);
    }

    #pragma unroll
    for (int r = 0; r < 5; ++r) {
        float* wp = Wout + (size_t)(i0 + ty + 16 * r) * N_ROWS + j0 + 2 * tx;
        float zr = 0.f;
        #pragma unroll
        for (int c = 0; c < CP; ++c) {
            const ull ap2 = fadd2(a2[r][c], eps2);
            float a0, a1, d0, d1;
            f2up(ap2, a0, a1);
            f2up(acc[r][c], d0, d1);
            float lg0, lg1, u0, u1;
            asm("lg2.approx.f32 %0, %1;" : "=f"(lg0) : "f"(a0));
            asm("lg2.approx.f32 %0, %1;" : "=f"(lg1) : "f"(a1));
            const float t0 = fmaf(kA, lg0, d0);
            const float t1 = fmaf(kA, lg1, d1);
            asm("ex2.approx.f32 %0, %1;" : "=f"(u0) : "f"(t0));
            asm("ex2.approx.f32 %0, %1;" : "=f"(u1) : "f"(t1));
            if (WRITE) *(float2*)(wp + 32 * c) = make_float2(u0 * invz[r], u1 * invz[r]);
            else       zr += u0 + u1;
        }
        if (!WRITE) zacc[r] += zr;
    }
}

template<bool WRITE>
__global__ void __launch_bounds__(256, 3) pass_kernel(
    const float* __restrict__ A, float* __restrict__ Wout,
    const float* __restrict__ p_log_tau, const float* __restrict__ p_raw_alpha)
{
    __shared__ __align__(16) ull   sHnI2[BM * EMB];      // (v,v) duplicated pairs
    __shared__ __align__(16) float sHnT[2][EMB * BN];    // kB-scaled HnT tiles

    const int tid   = threadIdx.x;
    const int tx    = tid & 15;
    const int ty    = tid >> 4;
    const int strip = blockIdx.x;
    const int i0    = blockIdx.y * BM;

    const float alpha = 1.f / (1.f + __expf(-p_raw_alpha[0]));
    const float kA    = alpha;
    const ull   eps2  = f2pk(1e-12f, 1e-12f);
    (void)p_log_tau;   // tau folded into g_HnTs by the encoder

    // stage this CTA's 80 Hn rows, duplicated into f32x2 pairs
    for (int t = tid; t < BM * EMB; t += 256) {
        const float v = g_Hn[i0 * EMB + t];
        sHnI2[t] = f2pk(v, v);
    }

    float invz[5] = {0, 0, 0, 0, 0};
    if (WRITE) {       // zreduce folded in: kernel-launch boundary orders g_Zpart
        #pragma unroll
        for (int r = 0; r < 5; ++r) {
            const int row = i0 + ty + 16 * r;
            invz[r] = 1.f / (g_Zpart[row] + g_Zpart[N_ROWS + row] + g_Zpart[2 * N_ROWS + row]);
        }
    }
    float zacc[5] = {0.f, 0.f, 0.f, 0.f, 0.f};

    prefetch_tile(&sHnT[0][0], strip * BN);
    int buf = 0;
    for (int jt = strip; jt < NJT; jt += STRIPS) {
        const int nxt = jt + STRIPS;
        if (nxt < NJT) {
            prefetch_tile(&sHnT[buf ^ 1][0], nxt * BN);
            asm volatile("cp.async.wait_group 1;" ::: "memory");
        } else {
            asm volatile("cp.async.wait_group 0;" ::: "memory");
        }
        __syncthreads();
        const float* sT = &sHnT[buf][0];
        if (jt == NJT - 1) {
            // last tile: exactly 16 real cols = 8 pairs -> tx<8 active, no other predicates
            if (tx < 8)
                tile_compute<1, WRITE>(A, Wout, sHnI2, sT, i0, jt * BN, ty, tx, kA, eps2, zacc, invz);
        } else {
            #pragma unroll 1
            for (int h = 0; h < 2; ++h)   // two 64-col halves: halves register tile -> occ 3
                tile_compute<2, WRITE>(A, Wout, sHnI2, sT + 64 * h, i0, jt * BN + 64 * h,
                                       ty, tx, kA, eps2, zacc, invz);
        }
        __syncthreads();
        buf ^= 1;
    }

    if (!WRITE) {
        #pragma unroll
        for (int r = 0; r < 5; ++r) {
            float z = zacc[r];
            z += __shfl_xor_sync(0xffffffffu, z, 1);
            z += __shfl_xor_sync(0xffffffffu, z, 2);
            z += __shfl_xor_sync(0xffffffffu, z, 4);
            z += __shfl_xor_sync(0xffffffffu, z, 8);
            if (tx == 0) g_Zpart[strip * N_ROWS + i0 + ty + 16 * r] = z;
        }
    }
}

// ======================================================================
extern "C" void kernel_launch(void* const* d_in, const int* in_sizes, int n_in,
                              void* d_out, int out_size)
{
    (void)in_sizes; (void)n_in; (void)out_size;
    const float* X         = (const float*)d_in[0];
    const float* A         = (const float*)d_in[1];
    const float* W1        = (const float*)d_in[2];
    const float* b1        = (const float*)d_in[3];
    const float* W2        = (const float*)d_in[4];
    const float* b2        = (const float*)d_in[5];
    const float* log_tau   = (const float*)d_in[6];
    const float* raw_alpha = (const float*)d_in[7];

    float* out  = (float*)d_out;
    float* Wout = out;                                   // (N, N) first
    float* Hout = out + (size_t)N_ROWS * N_ROWS;         // (N, EMB) second

    encoder_kernel<<<NPAD / 8, 256>>>(X, W1, b1, W2, b2, Hout, log_tau, raw_alpha);
    pass_kernel<false><<<dim3(STRIPS, N_ROWS / BM), 256>>>(A, Wout, log_tau, raw_alpha);
    pass_kernel<true ><<<dim3(STRIPS, N_ROWS / BM), 256>>>(A, Wout, log_tau, raw_alpha);
}

// round 8
// speedup vs baseline: 1.2710x; 1.2334x over previous
#include <cuda_runtime.h>
#include <cuda_fp16.h>
#include <cstdint>

#define N_ROWS   10000
#define NPAD     10112          // padded for HnT tiles (10112 = 79*128)
#define D_IN     128
#define HID      32
#define EMB      16
#define NJT      79             // ceil(10000/128) column tiles
#define BM       80             // rows per CTA tile
#define BN       128            // cols per CTA tile
#define SROWS    2000           // rows per L2 strip (5 strips)
#define NSTRIP   5
#define JSTRIPS  16             // j-strips in pass1 -> 16 * 25 = 400 CTAs/launch

typedef unsigned long long ull;

// ---------------- static device scratch (no runtime allocations) ----------------
__device__ __align__(16) float g_Hn  [NPAD * EMB];       // normalized embeddings, row-major
__device__ __align__(16) float g_HnTs[EMB * NPAD];       // transposed, pre-scaled by kB
__device__ __align__(16) float g_Zpart[JSTRIPS * SROWS];
__device__ __align__(16) float g_invZ[SROWS];
__device__ __align__(16) __half g_u[(size_t)SROWS * N_ROWS];  // 40MB fp16 u' strip (L2-resident)

// ---------------- f32x2 helpers ----------------
__device__ __forceinline__ ull f2pk(float lo, float hi) {
    ull r; asm("mov.b64 %0, {%1, %2};" : "=l"(r) : "f"(lo), "f"(hi)); return r;
}
__device__ __forceinline__ void f2up(ull v, float& lo, float& hi) {
    asm("mov.b64 {%0, %1}, %2;" : "=f"(lo), "=f"(hi) : "l"(v));
}
__device__ __forceinline__ ull ffma2(ull a, ull b, ull c) {
    ull d; asm("fma.rn.f32x2 %0, %1, %2, %3;" : "=l"(d) : "l"(a), "l"(b), "l"(c)); return d;
}

// ======================================================================
// Kernel 1: encoder.  H = relu(X@W1 + b1)@W2 + b2 ; Hn = H / max(||H||,1e-12)
// 4-way split accumulators break the serial FFMA RAW chain.
// ======================================================================
__global__ void __launch_bounds__(256) encoder_kernel(
    const float* __restrict__ X, const float* __restrict__ W1,
    const float* __restrict__ b1, const float* __restrict__ W2,
    const float* __restrict__ b2, float* __restrict__ Hout,
    const float* __restrict__ p_log_tau, const float* __restrict__ p_raw_alpha)
{
    __shared__ float sW1[D_IN * HID];
    __shared__ float sW2[HID * EMB];
    __shared__ float sb1[HID];
    __shared__ float sb2[EMB];
    __shared__ float sX[8][D_IN];
    __shared__ float sH1[8][HID];

    const int tid = threadIdx.x;
    for (int i = tid; i < D_IN * HID; i += 256) sW1[i] = W1[i];
    for (int i = tid; i < HID * EMB;  i += 256) sW2[i] = W2[i];
    if (tid < HID) sb1[tid] = b1[tid];
    if (tid < EMB) sb2[tid] = b2[tid];
    __syncthreads();

    const int w    = tid >> 5;
    const int lane = tid & 31;
    const int row  = blockIdx.x * 8 + w;
    if (row >= NPAD) return;

    if (row >= N_ROWS) {
        if (lane < EMB) {
            g_Hn  [row * EMB + lane]  = 0.f;
            g_HnTs[lane * NPAD + row] = 0.f;
        }
        return;
    }

    #pragma unroll
    for (int q = 0; q < 4; ++q) sX[w][lane + 32 * q] = X[(size_t)row * D_IN + lane + 32 * q];
    __syncwarp();

    // hidden layer: lane u computes h1[u], 4 independent accumulators
    float s0 = sb1[lane], s1 = 0.f, s2 = 0.f, s3 = 0.f;
    #pragma unroll
    for (int k = 0; k < D_IN; k += 4) {
        s0 = fmaf(sX[w][k    ], sW1[(k    ) * HID + lane], s0);
        s1 = fmaf(sX[w][k + 1], sW1[(k + 1) * HID + lane], s1);
        s2 = fmaf(sX[w][k + 2], sW1[(k + 2) * HID + lane], s2);
        s3 = fmaf(sX[w][k + 3], sW1[(k + 3) * HID + lane], s3);
    }
    float h1 = fmaxf((s0 + s1) + (s2 + s3), 0.f);
    sH1[w][lane] = h1;
    __syncwarp();

    // output layer: lane e (both half-warps) computes h[e], 2 accumulators
    const int e = lane & 15;
    float t0 = sb2[e], t1 = 0.f;
    #pragma unroll
    for (int u = 0; u < HID; u += 2) {
        t0 = fmaf(sH1[w][u    ], sW2[(u    ) * EMB + e], t0);
        t1 = fmaf(sH1[w][u + 1], sW2[(u + 1) * EMB + e], t1);
    }
    const float h = t0 + t1;

    float ss = h * h;
    ss += __shfl_xor_sync(0xffffffffu, ss, 1);
    ss += __shfl_xor_sync(0xffffffffu, ss, 2);
    ss += __shfl_xor_sync(0xffffffffu, ss, 4);
    ss += __shfl_xor_sync(0xffffffffu, ss, 8);
    const float inv = 1.f / fmaxf(sqrtf(ss), 1e-12f);

    if (lane < EMB) {
        const float alpha = 1.f / (1.f + __expf(-p_raw_alpha[0]));
        const float tau   = fminf(fmaxf(__expf(p_log_tau[0]), 0.1f), 10.f);
        const float kB    = (1.f - alpha) / (tau * 0.6931471805599453f);
        Hout[(size_t)row * EMB + e] = h;
        g_Hn  [row * EMB + e]       = h * inv;
        g_HnTs[e * NPAD + row]      = h * inv * kB;
    }
}

// ======================================================================
// Pass 1 (per row-strip): u' = 2^( dot16 + kA*lg2(A+eps) + 4 ), fp16 -> g_u;
// Z partials accumulated per j-strip.  A reads evict-first (__ldcs).
// ======================================================================
__device__ __forceinline__ void prefetch_tile(float* dst, int j0)
{
    const int tid = threadIdx.x;
    #pragma unroll
    for (int q = 0; q < 2; ++q) {
        const int s  = tid + q * 256;
        const int k  = s >> 5;
        const int cw = s & 31;
        const float* src = g_HnTs + k * NPAD + j0 + 4 * cw;
        unsigned dsts = (unsigned)__cvta_generic_to_shared(dst + k * BN + 4 * cw);
        asm volatile("cp.async.ca.shared.global [%0], [%1], 16;" :: "r"(dsts), "l"(src) : "memory");
    }
    asm volatile("cp.async.commit_group;" ::: "memory");
}

template<int CP>
__device__ __forceinline__ void tile_u(
    const float* __restrict__ A, int row0,
    const ull* sHnI2, const float* sT,
    int i0, int j0, int ty, int tx,
    float kA, ull bias2, float zacc[5])
{
    // A pair-loads (LDG.64, evict-first) batched up front
    float2 a2[5][CP];
    #pragma unroll
    for (int r = 0; r < 5; ++r) {
        const float2* ap = (const float2*)(A + (size_t)(i0 + ty + 16 * r) * N_ROWS + j0 + 2 * tx);
        #pragma unroll
        for (int c = 0; c < CP; ++c) a2[r][c] = __ldcs(ap + 16 * c);
    }

    ull acc[5][CP];
    #pragma unroll
    for (int r = 0; r < 5; ++r)
        #pragma unroll
        for (int c = 0; c < CP; ++c) acc[r][c] = bias2;   // (+4,+4) exponent bias baked in

    #pragma unroll
    for (int k = 0; k < EMB; ++k) {
        ull av[5], bv[CP];
        #pragma unroll
        for (int r = 0; r < 5; ++r)  av[r] = sHnI2[(ty + 16 * r) * EMB + k];
        #pragma unroll
        for (int c = 0; c < CP; ++c) bv[c] = *(const ull*)(sT + k * BN + 2 * tx + 32 * c);
        #pragma unroll
        for (int r = 0; r < 5; ++r)
            #pragma unroll
            for (int c = 0; c < CP; ++c)
                acc[r][c] = ffma2(av[r], bv[c], acc[r][c]);
    }

    #pragma unroll
    for (int r = 0; r < 5; ++r) {
        const int lrow = i0 - row0 + ty + 16 * r;
        __half* up = g_u + (size_t)lrow * N_ROWS + j0 + 2 * tx;
        float zr = 0.f;
        #pragma unroll
        for (int c = 0; c < CP; ++c) {
            const float a0 = a2[r][c].x + 1e-12f;
            const float a1 = a2[r][c].y + 1e-12f;
            float d0, d1;
            f2up(acc[r][c], d0, d1);
            float lg0, lg1, u0, u1;
            asm("lg2.approx.f32 %0, %1;" : "=f"(lg0) : "f"(a0));
            asm("lg2.approx.f32 %0, %1;" : "=f"(lg1) : "f"(a1));
            const float e0 = fmaf(kA, lg0, d0);
            const float e1 = fmaf(kA, lg1, d1);
            asm("ex2.approx.f32 %0, %1;" : "=f"(u0) : "f"(e0));
            asm("ex2.approx.f32 %0, %1;" : "=f"(u1) : "f"(e1));
            *(half2*)(up + 32 * c) = __floats2half2_rn(u0, u1);
            zr += u0 + u1;
        }
        zacc[r] += zr;
    }
}

__global__ void __launch_bounds__(256, 3) upass_kernel(
    const float* __restrict__ A, int row0,
    const float* __restrict__ p_raw_alpha)
{
    __shared__ __align__(16) ull   sHnI2[BM * EMB];      // (v,v) duplicated pairs
    __shared__ __align__(16) float sHnT[2][EMB * BN];

    const int tid   = threadIdx.x;
    const int tx    = tid & 15;
    const int ty    = tid >> 4;
    const int strip = blockIdx.x;                        // [0, JSTRIPS)
    const int i0    = row0 + blockIdx.y * BM;

    const float kA    = 1.f / (1.f + __expf(-p_raw_alpha[0]));   // alpha
    const ull   bias2 = f2pk(4.f, 4.f);

    for (int t = tid; t < BM * EMB; t += 256) {
        const float v = g_Hn[i0 * EMB + t];
        sHnI2[t] = f2pk(v, v);
    }

    float zacc[5] = {0.f, 0.f, 0.f, 0.f, 0.f};

    prefetch_tile(&sHnT[0][0], strip * BN);
    int buf = 0;
    for (int jt = strip; jt < NJT; jt += JSTRIPS) {
        const int nxt = jt + JSTRIPS;
        if (nxt < NJT) {
            prefetch_tile(&sHnT[buf ^ 1][0], nxt * BN);
            asm volatile("cp.async.wait_group 1;" ::: "memory");
        } else {
            asm volatile("cp.async.wait_group 0;" ::: "memory");
        }
        __syncthreads();
        const float* sT = &sHnT[buf][0];
        if (jt == NJT - 1) {
            if (tx < 8)    // last tile: 16 real cols = 8 pairs
                tile_u<1>(A, row0, sHnI2, sT, i0, jt * BN, ty, tx, kA, bias2, zacc);
        } else {
            #pragma unroll 1
            for (int h = 0; h < 2; ++h)
                tile_u<2>(A, row0, sHnI2, sT + 64 * h, i0, jt * BN + 64 * h,
                          ty, tx, kA, bias2, zacc);
        }
        __syncthreads();
        buf ^= 1;
    }

    #pragma unroll
    for (int r = 0; r < 5; ++r) {
        float z = zacc[r];
        z += __shfl_xor_sync(0xffffffffu, z, 1);
        z += __shfl_xor_sync(0xffffffffu, z, 2);
        z += __shfl_xor_sync(0xffffffffu, z, 4);
        z += __shfl_xor_sync(0xffffffffu, z, 8);
        if (tx == 0) g_Zpart[strip * SROWS + (i0 - row0) + ty + 16 * r] = z;
    }
}

// ======================================================================
// zreduce: invZ for the strip (deterministic)
// ======================================================================
__global__ void zreduce_kernel()
{
    const int i = blockIdx.x * 256 + threadIdx.x;
    if (i < SROWS) {
        float z = 0.f;
        #pragma unroll
        for (int s = 0; s < JSTRIPS; ++s) z += g_Zpart[s * SROWS + i];
        g_invZ[i] = 1.f / z;
    }
}

// ======================================================================
// Pass 2 (per strip): W = u' * invZ.  u' from L2-resident scratch,
// W stored evict-first (__stcs).  Pure streaming, ~1.5 slots/elem.
// ======================================================================
__global__ void __launch_bounds__(256) scale_kernel(float* __restrict__ Wout, int row0)
{
    const int row = blockIdx.y;                           // local row in strip
    const int col = blockIdx.x * 2048 + threadIdx.x * 8;
    if (col >= N_ROWS) return;                            // partial last chunk
    const float iz = g_invZ[row];

    const uint4 raw = *(const uint4*)(g_u + (size_t)row * N_ROWS + col);
    const float2 f0 = __half22float2(*(const half2*)&raw.x);
    const float2 f1 = __half22float2(*(const half2*)&raw.y);
    const float2 f2 = __half22float2(*(const half2*)&raw.z);
    const float2 f3 = __half22float2(*(const half2*)&raw.w);

    float* wp = Wout + (size_t)(row0 + row) * N_ROWS + col;
    float4 w0 = make_float4(f0.x * iz, f0.y * iz, f1.x * iz, f1.y * iz);
    float4 w1 = make_float4(f2.x * iz, f2.y * iz, f3.x * iz, f3.y * iz);
    __stcs((float4*)wp,     w0);
    __stcs((float4*)wp + 1, w1);
}

// ======================================================================
extern "C" void kernel_launch(void* const* d_in, const int* in_sizes, int n_in,
                              void* d_out, int out_size)
{
    (void)in_sizes; (void)n_in; (void)out_size;
    const float* X         = (const float*)d_in[0];
    const float* A         = (const float*)d_in[1];
    const float* W1        = (const float*)d_in[2];
    const float* b1        = (const float*)d_in[3];
    const float* W2        = (const float*)d_in[4];
    const float* b2        = (const float*)d_in[5];
    const float* log_tau   = (const float*)d_in[6];
    const float* raw_alpha = (const float*)d_in[7];

    float* out  = (float*)d_out;
    float* Wout = out;                                   // (N, N) first
    float* Hout = out + (size_t)N_ROWS * N_ROWS;         // (N, EMB) second

    encoder_kernel<<<NPAD / 8, 256>>>(X, W1, b1, W2, b2, Hout, log_tau, raw_alpha);

    for (int s = 0; s < NSTRIP; ++s) {
        const int row0 = s * SROWS;
        upass_kernel<<<dim3(JSTRIPS, SROWS / BM), 256>>>(A, row0, raw_alpha);
        zreduce_kernel<<<(SROWS + 255) / 256, 256>>>();
        scale_kernel<<<dim3(5, SROWS), 256>>>(Wout, row0);
    }
}

// round 9
// speedup vs baseline: 1.2724x; 1.0011x over previous
#include <cuda_runtime.h>
#include <cuda_fp16.h>
#include <cstdint>

#define N_ROWS   10000
#define NPAD     10112          // padded for HnT tiles (10112 = 79*128)
#define D_IN     128
#define HID      32
#define EMB      16
#define NJT      79             // ceil(10000/128) column tiles
#define BM       80             // rows per CTA tile
#define BN       128            // cols per CTA tile
#define SROWS    2000           // rows per L2 strip (5 strips)
#define NSTRIP   5
#define JSTRIPS  16             // j-strips in pass1 -> 16 * 25 = 400 CTAs/launch

typedef unsigned long long ull;
struct __align__(16) ull2_t { ull x, y; };

// ---------------- static device scratch (no runtime allocations) ----------------
__device__ __align__(16) float g_Hn  [NPAD * EMB];       // normalized embeddings, row-major
__device__ __align__(16) float g_HnTs[EMB * NPAD];       // transposed, pre-scaled by kB
__device__ __align__(16) float g_Zpart[JSTRIPS * SROWS];
__device__ __align__(16) __half g_u[(size_t)SROWS * N_ROWS];  // 40MB fp16 u' strip (L2-resident)

// ---------------- f32x2 helpers ----------------
__device__ __forceinline__ ull f2pk(float lo, float hi) {
    ull r; asm("mov.b64 %0, {%1, %2};" : "=l"(r) : "f"(lo), "f"(hi)); return r;
}
__device__ __forceinline__ void f2up(ull v, float& lo, float& hi) {
    asm("mov.b64 {%0, %1}, %2;" : "=f"(lo), "=f"(hi) : "l"(v));
}
__device__ __forceinline__ ull ffma2(ull a, ull b, ull c) {
    ull d; asm("fma.rn.f32x2 %0, %1, %2, %3;" : "=l"(d) : "l"(a), "l"(b), "l"(c)); return d;
}

// ======================================================================
// Kernel 1: encoder.  H = relu(X@W1 + b1)@W2 + b2 ; Hn = H / max(||H||,1e-12)
// ======================================================================
__global__ void __launch_bounds__(256) encoder_kernel(
    const float* __restrict__ X, const float* __restrict__ W1,
    const float* __restrict__ b1, const float* __restrict__ W2,
    const float* __restrict__ b2, float* __restrict__ Hout,
    const float* __restrict__ p_log_tau, const float* __restrict__ p_raw_alpha)
{
    __shared__ float sW1[D_IN * HID];
    __shared__ float sW2[HID * EMB];
    __shared__ float sb1[HID];
    __shared__ float sb2[EMB];
    __shared__ float sX[8][D_IN];
    __shared__ float sH1[8][HID];

    const int tid = threadIdx.x;
    for (int i = tid; i < D_IN * HID; i += 256) sW1[i] = W1[i];
    for (int i = tid; i < HID * EMB;  i += 256) sW2[i] = W2[i];
    if (tid < HID) sb1[tid] = b1[tid];
    if (tid < EMB) sb2[tid] = b2[tid];
    __syncthreads();

    const int w    = tid >> 5;
    const int lane = tid & 31;
    const int row  = blockIdx.x * 8 + w;
    if (row >= NPAD) return;

    if (row >= N_ROWS) {
        if (lane < EMB) {
            g_Hn  [row * EMB + lane]  = 0.f;
            g_HnTs[lane * NPAD + row] = 0.f;
        }
        return;
    }

    #pragma unroll
    for (int q = 0; q < 4; ++q) sX[w][lane + 32 * q] = X[(size_t)row * D_IN + lane + 32 * q];
    __syncwarp();

    float s0 = sb1[lane], s1 = 0.f, s2 = 0.f, s3 = 0.f;
    #pragma unroll
    for (int k = 0; k < D_IN; k += 4) {
        s0 = fmaf(sX[w][k    ], sW1[(k    ) * HID + lane], s0);
        s1 = fmaf(sX[w][k + 1], sW1[(k + 1) * HID + lane], s1);
        s2 = fmaf(sX[w][k + 2], sW1[(k + 2) * HID + lane], s2);
        s3 = fmaf(sX[w][k + 3], sW1[(k + 3) * HID + lane], s3);
    }
    float h1 = fmaxf((s0 + s1) + (s2 + s3), 0.f);
    sH1[w][lane] = h1;
    __syncwarp();

    const int e = lane & 15;
    float t0 = sb2[e], t1 = 0.f;
    #pragma unroll
    for (int u = 0; u < HID; u += 2) {
        t0 = fmaf(sH1[w][u    ], sW2[(u    ) * EMB + e], t0);
        t1 = fmaf(sH1[w][u + 1], sW2[(u + 1) * EMB + e], t1);
    }
    const float h = t0 + t1;

    float ss = h * h;
    ss += __shfl_xor_sync(0xffffffffu, ss, 1);
    ss += __shfl_xor_sync(0xffffffffu, ss, 2);
    ss += __shfl_xor_sync(0xffffffffu, ss, 4);
    ss += __shfl_xor_sync(0xffffffffu, ss, 8);
    const float inv = 1.f / fmaxf(sqrtf(ss), 1e-12f);

    if (lane < EMB) {
        const float alpha = 1.f / (1.f + __expf(-p_raw_alpha[0]));
        const float tau   = fminf(fmaxf(__expf(p_log_tau[0]), 0.1f), 10.f);
        const float kB    = (1.f - alpha) / (tau * 0.6931471805599453f);
        Hout[(size_t)row * EMB + e] = h;
        g_Hn  [row * EMB + e]       = h * inv;
        g_HnTs[e * NPAD + row]      = h * inv * kB;
    }
}

// ======================================================================
// Pass 1 (per row-strip): u' = 2^( dot16 + kA*lg2(A+eps) + 4 ), fp16 -> g_u;
// Z partials per j-strip.  Thread covers rows i0+ty+16r, cols j0+4tx (quad).
// A: LDG.128 evict-first; bv: single LDS.128 per k; u': STG.64.
// ======================================================================
__device__ __forceinline__ void prefetch_tile(float* dst, int j0)
{
    const int tid = threadIdx.x;
    #pragma unroll
    for (int q = 0; q < 2; ++q) {
        const int s  = tid + q * 256;
        const int k  = s >> 5;
        const int cw = s & 31;
        const float* src = g_HnTs + k * NPAD + j0 + 4 * cw;
        unsigned dsts = (unsigned)__cvta_generic_to_shared(dst + k * BN + 4 * cw);
        asm volatile("cp.async.ca.shared.global [%0], [%1], 16;" :: "r"(dsts), "l"(src) : "memory");
    }
    asm volatile("cp.async.commit_group;" ::: "memory");
}

// one 64-col half-tile: 16 threads x 4 contiguous cols each (cols j0 + 4*tx)
__device__ __forceinline__ void tile_u(
    const float* __restrict__ A, int row0,
    const ull* sHnI2, const float* sT,
    int i0, int j0, int ty, int tx,
    float kA, ull bias2, float zacc[5])
{
    // batched A quad-loads (LDG.128, evict-first)
    float4 a4[5];
    #pragma unroll
    for (int r = 0; r < 5; ++r)
        a4[r] = __ldcs((const float4*)(A + (size_t)(i0 + ty + 16 * r) * N_ROWS + j0 + 4 * tx));

    ull acc[5][2];
    #pragma unroll
    for (int r = 0; r < 5; ++r) { acc[r][0] = bias2; acc[r][1] = bias2; }

    #pragma unroll
    for (int k = 0; k < EMB; ++k) {
        ull av[5];
        #pragma unroll
        for (int r = 0; r < 5; ++r) av[r] = sHnI2[(ty + 16 * r) * EMB + k];
        const ull2_t bv = *(const ull2_t*)(sT + k * BN + 4 * tx);     // LDS.128 = 2 col-pairs
        #pragma unroll
        for (int r = 0; r < 5; ++r) {
            acc[r][0] = ffma2(av[r], bv.x, acc[r][0]);
            acc[r][1] = ffma2(av[r], bv.y, acc[r][1]);
        }
    }

    #pragma unroll
    for (int r = 0; r < 5; ++r) {
        const int lrow = i0 - row0 + ty + 16 * r;
        float d0, d1, d2, d3;
        f2up(acc[r][0], d0, d1);
        f2up(acc[r][1], d2, d3);
        float lg0, lg1, lg2v, lg3, u0, u1, u2, u3;
        asm("lg2.approx.f32 %0, %1;" : "=f"(lg0)  : "f"(a4[r].x + 1e-12f));
        asm("lg2.approx.f32 %0, %1;" : "=f"(lg1)  : "f"(a4[r].y + 1e-12f));
        asm("lg2.approx.f32 %0, %1;" : "=f"(lg2v) : "f"(a4[r].z + 1e-12f));
        asm("lg2.approx.f32 %0, %1;" : "=f"(lg3)  : "f"(a4[r].w + 1e-12f));
        const float e0 = fmaf(kA, lg0,  d0);
        const float e1 = fmaf(kA, lg1,  d1);
        const float e2 = fmaf(kA, lg2v, d2);
        const float e3 = fmaf(kA, lg3,  d3);
        asm("ex2.approx.f32 %0, %1;" : "=f"(u0) : "f"(e0));
        asm("ex2.approx.f32 %0, %1;" : "=f"(u1) : "f"(e1));
        asm("ex2.approx.f32 %0, %1;" : "=f"(u2) : "f"(e2));
        asm("ex2.approx.f32 %0, %1;" : "=f"(u3) : "f"(e3));
        const half2 h01 = __floats2half2_rn(u0, u1);
        const half2 h23 = __floats2half2_rn(u2, u3);
        uint2 pk;
        pk.x = *(const unsigned*)&h01;
        pk.y = *(const unsigned*)&h23;
        *(uint2*)(g_u + (size_t)lrow * N_ROWS + j0 + 4 * tx) = pk;    // STG.64
        zacc[r] += (u0 + u1) + (u2 + u3);
    }
}

__global__ void __launch_bounds__(256, 3) upass_kernel(
    const float* __restrict__ A, int row0,
    const float* __restrict__ p_raw_alpha)
{
    __shared__ __align__(16) ull   sHnI2[BM * EMB];      // (v,v) duplicated pairs
    __shared__ __align__(16) float sHnT[2][EMB * BN];

    const int tid   = threadIdx.x;
    const int tx    = tid & 15;
    const int ty    = tid >> 4;
    const int strip = blockIdx.x;                        // [0, JSTRIPS)
    const int i0    = row0 + blockIdx.y * BM;

    const float kA    = 1.f / (1.f + __expf(-p_raw_alpha[0]));   // alpha
    const ull   bias2 = f2pk(4.f, 4.f);

    for (int t = tid; t < BM * EMB; t += 256) {
        const float v = g_Hn[i0 * EMB + t];
        sHnI2[t] = f2pk(v, v);
    }

    float zacc[5] = {0.f, 0.f, 0.f, 0.f, 0.f};

    prefetch_tile(&sHnT[0][0], strip * BN);
    int buf = 0;
    for (int jt = strip; jt < NJT; jt += JSTRIPS) {
        const int nxt = jt + JSTRIPS;
        if (nxt < NJT) {
            prefetch_tile(&sHnT[buf ^ 1][0], nxt * BN);
            asm volatile("cp.async.wait_group 1;" ::: "memory");
        } else {
            asm volatile("cp.async.wait_group 0;" ::: "memory");
        }
        __syncthreads();
        const float* sT = &sHnT[buf][0];
        if (jt == NJT - 1) {
            if (tx < 4)    // last tile: 16 real cols = 4 quads
                tile_u(A, row0, sHnI2, sT, i0, jt * BN, ty, tx, kA, bias2, zacc);
        } else {
            #pragma unroll 1
            for (int h = 0; h < 2; ++h)
                tile_u(A, row0, sHnI2, sT + 64 * h, i0, jt * BN + 64 * h,
                       ty, tx, kA, bias2, zacc);
        }
        __syncthreads();
        buf ^= 1;
    }

    #pragma unroll
    for (int r = 0; r < 5; ++r) {
        float z = zacc[r];
        z += __shfl_xor_sync(0xffffffffu, z, 1);
        z += __shfl_xor_sync(0xffffffffu, z, 2);
        z += __shfl_xor_sync(0xffffffffu, z, 4);
        z += __shfl_xor_sync(0xffffffffu, z, 8);
        if (tx == 0) g_Zpart[strip * SROWS + (i0 - row0) + ty + 16 * r] = z;
    }
}

// ======================================================================
// Pass 2 (per strip): W = u' * invZ.  One row per CTA; 5 batched uint4
// loads per thread (MLP), __stcs float4 stores.  invZ computed inline
// (16 uniform partial loads) -- no separate zreduce launch.
// ======================================================================
__global__ void __launch_bounds__(256) scale_kernel(float* __restrict__ Wout, int row0)
{
    const int row = blockIdx.x;                           // local row in strip
    const int tid = threadIdx.x;

    float z = 0.f;
    #pragma unroll
    for (int s = 0; s < JSTRIPS; ++s) z += g_Zpart[s * SROWS + row];
    const float iz = 1.f / z;

    const uint4* up = (const uint4*)(g_u + (size_t)row * N_ROWS);   // 1250 uint4 per row
    float*       wp = Wout + (size_t)(row0 + row) * N_ROWS;

    uint4 raw[5];
    #pragma unroll
    for (int it = 0; it < 5; ++it) {
        const int idx = tid + 256 * it;
        if (idx < 1250) raw[it] = __ldcs(up + idx);
    }
    #pragma unroll
    for (int it = 0; it < 5; ++it) {
        const int idx = tid + 256 * it;
        if (idx < 1250) {
            const float2 f0 = __half22float2(*(const half2*)&raw[it].x);
            const float2 f1 = __half22float2(*(const half2*)&raw[it].y);
            const float2 f2 = __half22float2(*(const half2*)&raw[it].z);
            const float2 f3 = __half22float2(*(const half2*)&raw[it].w);
            __stcs((float4*)(wp + idx * 8),     make_float4(f0.x * iz, f0.y * iz, f1.x * iz, f1.y * iz));
            __stcs((float4*)(wp + idx * 8) + 1, make_float4(f2.x * iz, f2.y * iz, f3.x * iz, f3.y * iz));
        }
    }
}

// ======================================================================
extern "C" void kernel_launch(void* const* d_in, const int* in_sizes, int n_in,
                              void* d_out, int out_size)
{
    (void)in_sizes; (void)n_in; (void)out_size;
    const float* X         = (const float*)d_in[0];
    const float* A         = (const float*)d_in[1];
    const float* W1        = (const float*)d_in[2];
    const float* b1        = (const float*)d_in[3];
    const float* W2        = (const float*)d_in[4];
    const float* b2        = (const float*)d_in[5];
    const float* log_tau   = (const float*)d_in[6];
    const float* raw_alpha = (const float*)d_in[7];

    float* out  = (float*)d_out;
    float* Wout = out;                                   // (N, N) first
    float* Hout = out + (size_t)N_ROWS * N_ROWS;         // (N, EMB) second

    encoder_kernel<<<NPAD / 8, 256>>>(X, W1, b1, W2, b2, Hout, log_tau, raw_alpha);

    for (int s = 0; s < NSTRIP; ++s) {
        const int row0 = s * SROWS;
        upass_kernel<<<dim3(JSTRIPS, SROWS / BM), 256>>>(A, row0, raw_alpha);
        scale_kernel<<<SROWS, 256>>>(Wout, row0);
    }
}